// round 4
// baseline (speedup 1.0000x reference)
#include <cuda_runtime.h>

#define B_   32
#define S_   512
#define E_   8
#define H_   768
#define KG_  100
#define MH_  1000
#define NROW (B_*E_)     /* 256 */
#define KSPLIT 6
#define KC   167         /* ceil(1000/6), zero-padded */

typedef unsigned long long u64;

// Scratch (device globals — no allocation allowed)
__device__ float g_Hs[NROW * MH_];                       // 256x1000 post-relu hidden
__device__ __align__(16) float g_ENT[KSPLIT][NROW * H_]; // K-split partials of ent

// ---- packed fp32x2 helpers (sm_100+ PTX) ----------------------------------
__device__ __forceinline__ u64 pk2(float a, float b) {
    u64 r; asm("mov.b64 %0, {%1,%2};" : "=l"(r) : "f"(a), "f"(b)); return r;
}
__device__ __forceinline__ u64 fma2(u64 a, u64 b, u64 c) {
    u64 d; asm("fma.rn.f32x2 %0, %1, %2, %3;" : "=l"(d) : "l"(a), "l"(b), "l"(c)); return d;
}
__device__ __forceinline__ float2 up2(u64 v) {
    float2 f; asm("mov.b64 {%0,%1}, %2;" : "=f"(f.x), "=f"(f.y) : "l"(v)); return f;
}

// ---------------------------------------------------------------------------
// K1: Hs = relu(X @ W1 + b1)   X:[256,100]  W1:[100,1000]
// grid (4, 64): x = 256-col group, y = 4-row tile. block 256. (round-2 form)
// ---------------------------------------------------------------------------
__global__ void __launch_bounds__(256) k1_mlp1(const float* __restrict__ X,
                                               const float* __restrict__ W1,
                                               const float* __restrict__ b1) {
    __shared__ u64 xp[2][KG_];   // row pairs duplicated per k
    const int rb = blockIdx.y * 4;
    const int j  = blockIdx.x * 256 + threadIdx.x;

    for (int idx = threadIdx.x; idx < 2 * KG_; idx += 256) {
        int p = idx / KG_, k = idx - p * KG_;
        xp[p][k] = pk2(X[(rb + 2*p) * KG_ + k], X[(rb + 2*p + 1) * KG_ + k]);
    }
    __syncthreads();

    if (j < MH_) {
        const float bj = b1[j];
        u64 acc0 = pk2(bj, bj);
        u64 acc1 = acc0;

        #pragma unroll 10
        for (int k = 0; k < KG_; k++) {
            float w = W1[k * MH_ + j];
            u64 wp = pk2(w, w);
            acc0 = fma2(xp[0][k], wp, acc0);
            acc1 = fma2(xp[1][k], wp, acc1);
        }
        float2 a0 = up2(acc0), a1 = up2(acc1);
        g_Hs[(rb + 0) * MH_ + j] = fmaxf(a0.x, 0.0f);
        g_Hs[(rb + 1) * MH_ + j] = fmaxf(a0.y, 0.0f);
        g_Hs[(rb + 2) * MH_ + j] = fmaxf(a1.x, 0.0f);
        g_Hs[(rb + 3) * MH_ + j] = fmaxf(a1.y, 0.0f);
    }
}

// ---------------------------------------------------------------------------
// K2: ENT_part[kz] = Hs[:, kchunk] @ W2[kchunk, :]  (+ b2 folded into kz==0)
// M=256, N=768, K=1000. grid (6, 8, 6) = 288 blocks (2/SM). block 256:
// tx -> 4 cols (1 float4 of W2), ty -> 4 rows. 8 FFMA2 per k per thread.
// h stored in smem as DUPLICATED f32x2 pairs -> LDS.128 feeds FFMA2 directly.
// No register pipeline; latency hidden by 16 warps/SM.
// ---------------------------------------------------------------------------
__global__ void __launch_bounds__(256) k2_mlp2(const float* __restrict__ W2,
                                               const float* __restrict__ b2) {
    __shared__ u64 hd[KC][34];   // [k][row] duplicated pairs, padded stride

    const int cb = blockIdx.x * 128;
    const int rb = blockIdx.y * 32;
    const int kz = blockIdx.z;
    const int kb = kz * KC;
    const int tid = threadIdx.x;

    // Stage 32 x KC slice (coalesced along k), duplicated into pairs; zero-pad.
    for (int idx = tid; idx < 32 * KC; idx += 256) {
        int r = idx / KC, k = idx - r * KC;
        int kk = kb + k;
        float h = (kk < MH_) ? g_Hs[(rb + r) * MH_ + kk] : 0.0f;
        hd[k][r] = pk2(h, h);
    }
    __syncthreads();

    const int tx = tid & 31;
    const int ty = tid >> 5;
    const int r0 = ty * 4;
    const int col = cb + tx * 4;

    u64 acc[4][2];   // [row][col-pair]
    if (kz == 0) {
        float4 bv = *(const float4*)(b2 + col);
        u64 p0 = pk2(bv.x, bv.y), p1 = pk2(bv.z, bv.w);
        #pragma unroll
        for (int i = 0; i < 4; i++) { acc[i][0] = p0; acc[i][1] = p1; }
    } else {
        #pragma unroll
        for (int i = 0; i < 4; i++) { acc[i][0] = 0ULL; acc[i][1] = 0ULL; }
    }

    const float4* __restrict__ W24 = (const float4*)W2;

    #pragma unroll 4
    for (int k = 0; k < KC; k++) {
        int kk = kb + k;
        if (kk >= MH_) break;
        u64 h0 = hd[k][r0 + 0];
        u64 h1 = hd[k][r0 + 1];
        u64 h2 = hd[k][r0 + 2];
        u64 h3 = hd[k][r0 + 3];

        float4 w = W24[((long long)kk * H_ + col) >> 2];
        u64 wp0 = pk2(w.x, w.y), wp1 = pk2(w.z, w.w);

        acc[0][0] = fma2(h0, wp0, acc[0][0]);
        acc[0][1] = fma2(h0, wp1, acc[0][1]);
        acc[1][0] = fma2(h1, wp0, acc[1][0]);
        acc[1][1] = fma2(h1, wp1, acc[1][1]);
        acc[2][0] = fma2(h2, wp0, acc[2][0]);
        acc[2][1] = fma2(h2, wp1, acc[2][1]);
        acc[3][0] = fma2(h3, wp0, acc[3][0]);
        acc[3][1] = fma2(h3, wp1, acc[3][1]);
    }

    float* dst = g_ENT[kz];
    #pragma unroll
    for (int i = 0; i < 4; i++) {
        int r = rb + r0 + i;
        float2 a0 = up2(acc[i][0]), a1 = up2(acc[i][1]);
        *(float4*)(dst + r * H_ + col) = make_float4(a0.x, a0.y, a1.x, a1.y);
    }
}

// ---------------------------------------------------------------------------
// kR: reduce the 6 K-split partials in place into g_ENT[0].
// ---------------------------------------------------------------------------
__global__ void __launch_bounds__(256) kR_reduce() {
    int i = blockIdx.x * 512 + threadIdx.x;
    #pragma unroll
    for (int t = 0; t < 2; t++, i += 256) {
        float4 a = ((const float4*)g_ENT[0])[i];
        #pragma unroll
        for (int p = 1; p < KSPLIT; p++) {
            float4 b = ((const float4*)g_ENT[p])[i];
            a.x += b.x; a.y += b.y; a.z += b.z; a.w += b.w;
        }
        ((float4*)g_ENT[0])[i] = a;
    }
}

// ---------------------------------------------------------------------------
// K3: out[b,s,:] = word_embedding[ids[b,s]] + sum_e mask[b,e,s] * ent[b*E+e,:]
// 4 rows per block -> 4096 blocks x 192 threads.
// Each thread issues its 4 independent row gathers (MLP=4) BEFORE the mask
// barrier; warp 0 loads the 32 mask scalars + ballots a nonzero bitmask in
// parallel with those loads. Entity rows reused across all 4 rows.
// ---------------------------------------------------------------------------
__global__ void __launch_bounds__(192) k3_fuse(const int*   __restrict__ ids,
                                               const float* __restrict__ mask,
                                               const float* __restrict__ we,
                                               float*       __restrict__ out) {
    const int rblk = blockIdx.x;          // 4096
    const int b    = rblk >> 7;           // 128 row-quads per batch
    const int s0   = (rblk & 127) << 2;
    const int row0 = b * S_ + s0;
    const int tid  = threadIdx.x;

    __shared__ float    sm[E_][4];        // mask[e][rr]
    __shared__ unsigned sflag;            // bit (e*4+rr) = nonzero

    // ids: 4 broadcast loads, then fire all 4 gathers (independent LDG.128s)
    int wid0 = __ldg(ids + row0 + 0);
    int wid1 = __ldg(ids + row0 + 1);
    int wid2 = __ldg(ids + row0 + 2);
    int wid3 = __ldg(ids + row0 + 3);

    const float4* __restrict__ we4 = (const float4*)we;
    float4 v0 = we4[(long long)wid0 * (H_ / 4) + tid];
    float4 v1 = we4[(long long)wid1 * (H_ / 4) + tid];
    float4 v2 = we4[(long long)wid2 * (H_ / 4) + tid];
    float4 v3 = we4[(long long)wid3 * (H_ / 4) + tid];

    // Meanwhile warp 0 fetches the 8x4 mask scalars and builds the bitmask.
    if (tid < 32) {
        int e  = tid >> 2;
        int rr = tid & 3;
        float m = __ldg(mask + (b * E_ + e) * S_ + s0 + rr);
        sm[e][rr] = m;
        unsigned bal = __ballot_sync(0xffffffffu, m != 0.0f);
        if (tid == 0) sflag = bal;
    }
    __syncthreads();

    const unsigned flag = sflag;
    if (flag) {
        const float4* __restrict__ ent4 = (const float4*)g_ENT[0];
        #pragma unroll
        for (int e = 0; e < E_; e++) {
            unsigned f4 = (flag >> (e * 4)) & 0xFu;
            if (f4) {
                float4 p = ent4[(b * E_ + e) * (H_ / 4) + tid];
                if (f4 & 1u) { float m = sm[e][0];
                    v0.x = fmaf(m, p.x, v0.x); v0.y = fmaf(m, p.y, v0.y);
                    v0.z = fmaf(m, p.z, v0.z); v0.w = fmaf(m, p.w, v0.w); }
                if (f4 & 2u) { float m = sm[e][1];
                    v1.x = fmaf(m, p.x, v1.x); v1.y = fmaf(m, p.y, v1.y);
                    v1.z = fmaf(m, p.z, v1.z); v1.w = fmaf(m, p.w, v1.w); }
                if (f4 & 4u) { float m = sm[e][2];
                    v2.x = fmaf(m, p.x, v2.x); v2.y = fmaf(m, p.y, v2.y);
                    v2.z = fmaf(m, p.z, v2.z); v2.w = fmaf(m, p.w, v2.w); }
                if (f4 & 8u) { float m = sm[e][3];
                    v3.x = fmaf(m, p.x, v3.x); v3.y = fmaf(m, p.y, v3.y);
                    v3.z = fmaf(m, p.z, v3.z); v3.w = fmaf(m, p.w, v3.w); }
            }
        }
    }

    float4* __restrict__ out4 = (float4*)out;
    out4[(long long)(row0 + 0) * (H_ / 4) + tid] = v0;
    out4[(long long)(row0 + 1) * (H_ / 4) + tid] = v1;
    out4[(long long)(row0 + 2) * (H_ / 4) + tid] = v2;
    out4[(long long)(row0 + 3) * (H_ / 4) + tid] = v3;
}

// ---------------------------------------------------------------------------
extern "C" void kernel_launch(void* const* d_in, const int* in_sizes, int n_in,
                              void* d_out, int out_size) {
    const int*   ids  = (const int*)  d_in[0];   // input_ids        [32,512]
    const float* X    = (const float*)d_in[1];   // entity_embeddings[32,8,100]
    const float* msk  = (const float*)d_in[2];   // entity_mask      [32,8,512]
    const float* we   = (const float*)d_in[3];   // word_embedding   [30522,768]
    const float* W1   = (const float*)d_in[4];   // [100,1000]
    const float* b1   = (const float*)d_in[5];   // [1000]
    const float* W2   = (const float*)d_in[6];   // [1000,768]
    const float* b2   = (const float*)d_in[7];   // [768]
    float* out = (float*)d_out;                  // [32,512,768]

    k1_mlp1<<<dim3(4, 64), 256>>>(X, W1, b1);
    k2_mlp2<<<dim3(6, 8, KSPLIT), 256>>>(W2, b2);
    kR_reduce<<<96, 256>>>();
    k3_fuse<<<4096, 192>>>(ids, msk, we, out);
}

// round 5
// speedup vs baseline: 1.3586x; 1.3586x over previous
#include <cuda_runtime.h>

#define B_   32
#define S_   512
#define E_   8
#define H_   768
#define KG_  100
#define MH_  1000
#define NROW (B_*E_)     /* 256 */
#define KSPLIT 6
#define KC   167         /* ceil(1000/6) */
#define HDK  168         /* KC padded to multiple of 4 */

typedef unsigned long long u64;

// Scratch (device globals — no allocation allowed)
__device__ float g_Hs[NROW * MH_];                       // 256x1000 post-relu hidden
__device__ __align__(16) float g_ENT[KSPLIT][NROW * H_]; // K-split partials of ent

// ---- packed fp32x2 helpers (sm_100+ PTX) ----------------------------------
__device__ __forceinline__ u64 pk2(float a, float b) {
    u64 r; asm("mov.b64 %0, {%1,%2};" : "=l"(r) : "f"(a), "f"(b)); return r;
}
__device__ __forceinline__ u64 fma2(u64 a, u64 b, u64 c) {
    u64 d; asm("fma.rn.f32x2 %0, %1, %2, %3;" : "=l"(d) : "l"(a), "l"(b), "l"(c)); return d;
}
__device__ __forceinline__ float2 up2(u64 v) {
    float2 f; asm("mov.b64 {%0,%1}, %2;" : "=f"(f.x), "=f"(f.y) : "l"(v)); return f;
}

// ---------------------------------------------------------------------------
// K1: Hs = relu(X @ W1 + b1)   X:[256,100]  W1:[100,1000]
// grid (4, 64): x = 256-col group, y = 4-row tile. block 256. (round-2 form)
// ---------------------------------------------------------------------------
__global__ void __launch_bounds__(256) k1_mlp1(const float* __restrict__ X,
                                               const float* __restrict__ W1,
                                               const float* __restrict__ b1) {
    __shared__ u64 xp[2][KG_];   // row pairs duplicated per k
    const int rb = blockIdx.y * 4;
    const int j  = blockIdx.x * 256 + threadIdx.x;

    for (int idx = threadIdx.x; idx < 2 * KG_; idx += 256) {
        int p = idx / KG_, k = idx - p * KG_;
        xp[p][k] = pk2(X[(rb + 2*p) * KG_ + k], X[(rb + 2*p + 1) * KG_ + k]);
    }
    __syncthreads();

    if (j < MH_) {
        const float bj = b1[j];
        u64 acc0 = pk2(bj, bj);
        u64 acc1 = acc0;

        #pragma unroll 10
        for (int k = 0; k < KG_; k++) {
            float w = W1[k * MH_ + j];
            u64 wp = pk2(w, w);
            acc0 = fma2(xp[0][k], wp, acc0);
            acc1 = fma2(xp[1][k], wp, acc1);
        }
        float2 a0 = up2(acc0), a1 = up2(acc1);
        g_Hs[(rb + 0) * MH_ + j] = fmaxf(a0.x, 0.0f);
        g_Hs[(rb + 1) * MH_ + j] = fmaxf(a0.y, 0.0f);
        g_Hs[(rb + 2) * MH_ + j] = fmaxf(a1.x, 0.0f);
        g_Hs[(rb + 3) * MH_ + j] = fmaxf(a1.y, 0.0f);
    }
}

// ---------------------------------------------------------------------------
// K2: ENT_part[kz] = Hs[:, kchunk] @ W2[kchunk, :]  (+ b2 folded into kz==0)
// M=256, N=768, K=1000. grid (6, 8, 6) = 288 blocks (2/SM, 4 warps/SMSP).
// block 256: tx (0..31) -> 4 cols (1 float4 of W2), ty (0..7) -> 4 rows.
// h staged as plain floats, row-stride 33 -> conflict-free stores, broadcast
// loads (all lanes of a warp share ty). Inner loop: quads of 4 ks with all
// 4 W2 LDG.128s issued up-front (MLP=4/warp) before the FMA burst.
// ---------------------------------------------------------------------------
__global__ void __launch_bounds__(256) k2_mlp2(const float* __restrict__ W2,
                                               const float* __restrict__ b2) {
    __shared__ float hs[HDK][33];   // [k][row], pad -> conflict-free staging

    const int cb = blockIdx.x * 128;
    const int rb = blockIdx.y * 32;
    const int kz = blockIdx.z;
    const int kb = kz * KC;
    const int tid = threadIdx.x;

    // Stage 32 x HDK slice; consecutive threads -> consecutive k (same r):
    // gmem reads coalesced, smem writes stride-33 floats = conflict-free.
    for (int idx = tid; idx < 32 * HDK; idx += 256) {
        int r = idx / HDK, k = idx - r * HDK;
        int kk = kb + k;
        hs[k][r] = (k < KC && kk < MH_) ? g_Hs[(rb + r) * MH_ + kk] : 0.0f;
    }
    __syncthreads();

    const int tx = tid & 31;
    const int ty = tid >> 5;
    const int r0 = ty * 4;
    const int col = cb + tx * 4;

    u64 acc[4][2];   // [row][col-pair]
    if (kz == 0) {
        float4 bv = *(const float4*)(b2 + col);
        u64 p0 = pk2(bv.x, bv.y), p1 = pk2(bv.z, bv.w);
        #pragma unroll
        for (int i = 0; i < 4; i++) { acc[i][0] = p0; acc[i][1] = p1; }
    } else {
        #pragma unroll
        for (int i = 0; i < 4; i++) { acc[i][0] = 0ULL; acc[i][1] = 0ULL; }
    }

    const float4* __restrict__ W24 = (const float4*)W2;

    for (int q = 0; q < HDK / 4; q++) {
        const int k0 = q * 4;

        // Batch the 4 W2 row loads (independent LDG.128s, rows clamped
        // in-bounds; pad rows multiply h==0 so the value is irrelevant).
        float4 w[4];
        #pragma unroll
        for (int u = 0; u < 4; u++) {
            int kk = min(kb + k0 + u, MH_ - 1);
            w[u] = W24[((long long)kk * H_ + col) >> 2];
        }

        #pragma unroll
        for (int u = 0; u < 4; u++) {
            const int k = k0 + u;
            float h0 = hs[k][r0 + 0];
            float h1 = hs[k][r0 + 1];
            float h2 = hs[k][r0 + 2];
            float h3 = hs[k][r0 + 3];
            u64 wp0 = pk2(w[u].x, w[u].y);
            u64 wp1 = pk2(w[u].z, w[u].w);
            u64 hp0 = pk2(h0, h0);
            u64 hp1 = pk2(h1, h1);
            u64 hp2 = pk2(h2, h2);
            u64 hp3 = pk2(h3, h3);

            acc[0][0] = fma2(hp0, wp0, acc[0][0]);
            acc[0][1] = fma2(hp0, wp1, acc[0][1]);
            acc[1][0] = fma2(hp1, wp0, acc[1][0]);
            acc[1][1] = fma2(hp1, wp1, acc[1][1]);
            acc[2][0] = fma2(hp2, wp0, acc[2][0]);
            acc[2][1] = fma2(hp2, wp1, acc[2][1]);
            acc[3][0] = fma2(hp3, wp0, acc[3][0]);
            acc[3][1] = fma2(hp3, wp1, acc[3][1]);
        }
    }

    float* dst = g_ENT[kz];
    #pragma unroll
    for (int i = 0; i < 4; i++) {
        int r = rb + r0 + i;
        float2 a0 = up2(acc[i][0]), a1 = up2(acc[i][1]);
        *(float4*)(dst + r * H_ + col) = make_float4(a0.x, a0.y, a1.x, a1.y);
    }
}

// ---------------------------------------------------------------------------
// kR: reduce the 6 K-split partials in place into g_ENT[0].
// ---------------------------------------------------------------------------
__global__ void __launch_bounds__(256) kR_reduce() {
    int i = blockIdx.x * 512 + threadIdx.x;
    #pragma unroll
    for (int t = 0; t < 2; t++, i += 256) {
        float4 a = ((const float4*)g_ENT[0])[i];
        #pragma unroll
        for (int p = 1; p < KSPLIT; p++) {
            float4 b = ((const float4*)g_ENT[p])[i];
            a.x += b.x; a.y += b.y; a.z += b.z; a.w += b.w;
        }
        ((float4*)g_ENT[0])[i] = a;
    }
}

// ---------------------------------------------------------------------------
// K3: out[b,s,:] = word_embedding[ids[b,s]] + sum_e mask[b,e,s] * ent[b*E+e,:]
// 4 rows per block -> 4096 blocks x 192 threads. (round-4 form, measured 15.4us)
// ---------------------------------------------------------------------------
__global__ void __launch_bounds__(192) k3_fuse(const int*   __restrict__ ids,
                                               const float* __restrict__ mask,
                                               const float* __restrict__ we,
                                               float*       __restrict__ out) {
    const int rblk = blockIdx.x;          // 4096
    const int b    = rblk >> 7;           // 128 row-quads per batch
    const int s0   = (rblk & 127) << 2;
    const int row0 = b * S_ + s0;
    const int tid  = threadIdx.x;

    __shared__ float    sm[E_][4];        // mask[e][rr]
    __shared__ unsigned sflag;            // bit (e*4+rr) = nonzero

    int wid0 = __ldg(ids + row0 + 0);
    int wid1 = __ldg(ids + row0 + 1);
    int wid2 = __ldg(ids + row0 + 2);
    int wid3 = __ldg(ids + row0 + 3);

    const float4* __restrict__ we4 = (const float4*)we;
    float4 v0 = we4[(long long)wid0 * (H_ / 4) + tid];
    float4 v1 = we4[(long long)wid1 * (H_ / 4) + tid];
    float4 v2 = we4[(long long)wid2 * (H_ / 4) + tid];
    float4 v3 = we4[(long long)wid3 * (H_ / 4) + tid];

    if (tid < 32) {
        int e  = tid >> 2;
        int rr = tid & 3;
        float m = __ldg(mask + (b * E_ + e) * S_ + s0 + rr);
        sm[e][rr] = m;
        unsigned bal = __ballot_sync(0xffffffffu, m != 0.0f);
        if (tid == 0) sflag = bal;
    }
    __syncthreads();

    const unsigned flag = sflag;
    if (flag) {
        const float4* __restrict__ ent4 = (const float4*)g_ENT[0];
        #pragma unroll
        for (int e = 0; e < E_; e++) {
            unsigned f4 = (flag >> (e * 4)) & 0xFu;
            if (f4) {
                float4 p = ent4[(b * E_ + e) * (H_ / 4) + tid];
                if (f4 & 1u) { float m = sm[e][0];
                    v0.x = fmaf(m, p.x, v0.x); v0.y = fmaf(m, p.y, v0.y);
                    v0.z = fmaf(m, p.z, v0.z); v0.w = fmaf(m, p.w, v0.w); }
                if (f4 & 2u) { float m = sm[e][1];
                    v1.x = fmaf(m, p.x, v1.x); v1.y = fmaf(m, p.y, v1.y);
                    v1.z = fmaf(m, p.z, v1.z); v1.w = fmaf(m, p.w, v1.w); }
                if (f4 & 4u) { float m = sm[e][2];
                    v2.x = fmaf(m, p.x, v2.x); v2.y = fmaf(m, p.y, v2.y);
                    v2.z = fmaf(m, p.z, v2.z); v2.w = fmaf(m, p.w, v2.w); }
                if (f4 & 8u) { float m = sm[e][3];
                    v3.x = fmaf(m, p.x, v3.x); v3.y = fmaf(m, p.y, v3.y);
                    v3.z = fmaf(m, p.z, v3.z); v3.w = fmaf(m, p.w, v3.w); }
            }
        }
    }

    float4* __restrict__ out4 = (float4*)out;
    out4[(long long)(row0 + 0) * (H_ / 4) + tid] = v0;
    out4[(long long)(row0 + 1) * (H_ / 4) + tid] = v1;
    out4[(long long)(row0 + 2) * (H_ / 4) + tid] = v2;
    out4[(long long)(row0 + 3) * (H_ / 4) + tid] = v3;
}

// ---------------------------------------------------------------------------
extern "C" void kernel_launch(void* const* d_in, const int* in_sizes, int n_in,
                              void* d_out, int out_size) {
    const int*   ids  = (const int*)  d_in[0];   // input_ids        [32,512]
    const float* X    = (const float*)d_in[1];   // entity_embeddings[32,8,100]
    const float* msk  = (const float*)d_in[2];   // entity_mask      [32,8,512]
    const float* we   = (const float*)d_in[3];   // word_embedding   [30522,768]
    const float* W1   = (const float*)d_in[4];   // [100,1000]
    const float* b1   = (const float*)d_in[5];   // [1000]
    const float* W2   = (const float*)d_in[6];   // [1000,768]
    const float* b2   = (const float*)d_in[7];   // [768]
    float* out = (float*)d_out;                  // [32,512,768]

    k1_mlp1<<<dim3(4, 64), 256>>>(X, W1, b1);
    k2_mlp2<<<dim3(6, 8, KSPLIT), 256>>>(W2, b2);
    kR_reduce<<<96, 256>>>();
    k3_fuse<<<4096, 192>>>(ids, msk, we, out);
}

// round 6
// speedup vs baseline: 1.8011x; 1.3257x over previous
#include <cuda_runtime.h>

#define B_   32
#define S_   512
#define E_   8
#define H_   768
#define KG_  100
#define MH_  1000
#define NROW (B_*E_)     /* 256 */
#define KSPLIT 6
#define KC   167         /* ceil(1000/6) */
#define KPAD 168

typedef unsigned long long u64;

// Scratch (device globals — no allocation allowed)
__device__ float g_Hs[NROW * MH_];                       // 256x1000 post-relu hidden
__device__ __align__(16) float g_ENT[KSPLIT][NROW * H_]; // K-split partials of ent

// ---- packed fp32x2 helpers (sm_100+ PTX) ----------------------------------
__device__ __forceinline__ u64 pk2(float a, float b) {
    u64 r; asm("mov.b64 %0, {%1,%2};" : "=l"(r) : "f"(a), "f"(b)); return r;
}
__device__ __forceinline__ u64 fma2(u64 a, u64 b, u64 c) {
    u64 d; asm("fma.rn.f32x2 %0, %1, %2, %3;" : "=l"(d) : "l"(a), "l"(b), "l"(c)); return d;
}
__device__ __forceinline__ float2 up2(u64 v) {
    float2 f; asm("mov.b64 {%0,%1}, %2;" : "=f"(f.x), "=f"(f.y) : "l"(v)); return f;
}

#define SMEM1 (KG_*256*4 + 4*KG_*8)          /* 105600 B */
#define SMEM2 (KPAD*128*4 + 64*KPAD*8)       /* 172032 B */

// ---------------------------------------------------------------------------
// K1: Hs = relu(X @ W1 + b1)
// grid (4, 32): x = 256-col group, y = 8-row tile. block 256.
// W1 column-tile staged in smem (25 indep float4 loads/thread), compute loop
// never touches gmem.
// ---------------------------------------------------------------------------
__global__ void __launch_bounds__(256) k1_mlp1(const float* __restrict__ X,
                                               const float* __restrict__ W1,
                                               const float* __restrict__ b1) {
    extern __shared__ char smraw1[];
    float* sw1 = (float*)smraw1;                    // [100][256]
    u64*   xp  = (u64*)(smraw1 + KG_ * 256 * 4);    // [4][100] row-pair dups

    const int cb = blockIdx.x * 256;
    const int rb = blockIdx.y * 8;
    const int tid = threadIdx.x;

    const float4* __restrict__ W14 = (const float4*)W1;   // 250 f4 per row
    const int c4base = cb >> 2;

    #pragma unroll
    for (int i = 0; i < 25; i++) {                  // 100 rows x 64 f4
        int idx = tid + i * 256;
        int row = idx >> 6, c = idx & 63;
        float4 v = make_float4(0.f, 0.f, 0.f, 0.f);
        if (c4base + c < MH_ / 4)                   // full f4 in-bounds
            v = W14[row * (MH_ / 4) + c4base + c];
        *(float4*)(sw1 + row * 256 + c * 4) = v;
    }
    for (int idx = tid; idx < 4 * KG_; idx += 256) {
        int p = idx / KG_, k = idx - p * KG_;
        xp[p * KG_ + k] = pk2(X[(rb + 2*p) * KG_ + k], X[(rb + 2*p + 1) * KG_ + k]);
    }
    __syncthreads();

    const int j = cb + tid;
    if (j < MH_) {
        const float bj = b1[j];
        u64 acc0 = pk2(bj, bj);
        u64 acc1 = acc0, acc2 = acc0, acc3 = acc0;

        #pragma unroll 10
        for (int k = 0; k < KG_; k++) {
            float w = sw1[k * 256 + tid];
            u64 wp = pk2(w, w);
            acc0 = fma2(xp[0 * KG_ + k], wp, acc0);
            acc1 = fma2(xp[1 * KG_ + k], wp, acc1);
            acc2 = fma2(xp[2 * KG_ + k], wp, acc2);
            acc3 = fma2(xp[3 * KG_ + k], wp, acc3);
        }
        float2 a0 = up2(acc0), a1 = up2(acc1), a2 = up2(acc2), a3 = up2(acc3);
        g_Hs[(rb + 0) * MH_ + j] = fmaxf(a0.x, 0.0f);
        g_Hs[(rb + 1) * MH_ + j] = fmaxf(a0.y, 0.0f);
        g_Hs[(rb + 2) * MH_ + j] = fmaxf(a1.x, 0.0f);
        g_Hs[(rb + 3) * MH_ + j] = fmaxf(a1.y, 0.0f);
        g_Hs[(rb + 4) * MH_ + j] = fmaxf(a2.x, 0.0f);
        g_Hs[(rb + 5) * MH_ + j] = fmaxf(a2.y, 0.0f);
        g_Hs[(rb + 6) * MH_ + j] = fmaxf(a3.x, 0.0f);
        g_Hs[(rb + 7) * MH_ + j] = fmaxf(a3.y, 0.0f);
    }
}

// ---------------------------------------------------------------------------
// K2: ENT_part[kz] = Hs[:, kchunk] @ W2[kchunk, :]  (+ b2 folded into kz==0)
// grid (6, 4, 6) = 144 blocks (1/SM). block 256: tx -> 4 cols, ty -> 8 rows.
// W2 tile (167x128) AND h tile (64x167, duplicated f32x2 pairs) both staged
// in smem; inner loop = 1 LDS.128 + 8 broadcast LDS.64 + 16 FFMA2 per k.
// ---------------------------------------------------------------------------
__global__ void __launch_bounds__(256) k2_mlp2(const float* __restrict__ W2,
                                               const float* __restrict__ b2) {
    extern __shared__ char smraw2[];
    float* sw2 = (float*)smraw2;                    // [168][128]
    u64*   shd = (u64*)(smraw2 + KPAD * 128 * 4);   // [64][168] dup pairs

    const int cbase = blockIdx.x * 128;
    const int rb = blockIdx.y * 64;
    const int kz = blockIdx.z;
    const int kb = kz * KC;
    const int tid = threadIdx.x;
    const int tx = tid & 31;
    const int ty = tid >> 5;

    // Stage W2 tile: 168 rows x 32 f4 (21 indep f4 loads/thread).
    const float4* __restrict__ W24 = (const float4*)W2;
    #pragma unroll
    for (int i = 0; i < 21; i++) {
        int idx = tid + i * 256;
        int row = idx >> 5, c = idx & 31;
        int kk = kb + row;
        float4 v = make_float4(0.f, 0.f, 0.f, 0.f);
        if (row < KC && kk < MH_)
            v = W24[kk * (H_ / 4) + (cbase >> 2) + c];
        *(float4*)(sw2 + row * 128 + c * 4) = v;
    }

    // Stage h tile as duplicated pairs: warp ty handles rows ty, ty+8, ...
    #pragma unroll
    for (int rr = 0; rr < 8; rr++) {
        int r = rr * 8 + ty;
        const float* hrow = g_Hs + (rb + r) * MH_ + kb;
        for (int k = tx; k < KPAD; k += 32) {
            float v = (k < KC && kb + k < MH_) ? hrow[k] : 0.0f;
            shd[r * KPAD + k] = pk2(v, v);
        }
    }
    __syncthreads();

    const int col = cbase + tx * 4;
    const int r0 = ty * 8;

    u64 acc[8][2];
    if (kz == 0) {
        float4 bv = *(const float4*)(b2 + col);
        u64 p0 = pk2(bv.x, bv.y), p1 = pk2(bv.z, bv.w);
        #pragma unroll
        for (int i = 0; i < 8; i++) { acc[i][0] = p0; acc[i][1] = p1; }
    } else {
        #pragma unroll
        for (int i = 0; i < 8; i++) { acc[i][0] = 0ULL; acc[i][1] = 0ULL; }
    }

    #pragma unroll 4
    for (int k = 0; k < KPAD; k++) {
        float4 w = *(const float4*)(sw2 + k * 128 + tx * 4);
        u64 wp0 = pk2(w.x, w.y), wp1 = pk2(w.z, w.w);
        #pragma unroll
        for (int i = 0; i < 8; i++) {
            u64 h = shd[(r0 + i) * KPAD + k];       // broadcast LDS.64
            acc[i][0] = fma2(h, wp0, acc[i][0]);
            acc[i][1] = fma2(h, wp1, acc[i][1]);
        }
    }

    float* dst = g_ENT[kz];
    #pragma unroll
    for (int i = 0; i < 8; i++) {
        int r = rb + r0 + i;
        float2 a0 = up2(acc[i][0]), a1 = up2(acc[i][1]);
        *(float4*)(dst + r * H_ + col) = make_float4(a0.x, a0.y, a1.x, a1.y);
    }
}

// ---------------------------------------------------------------------------
// kR: reduce the 6 K-split partials in place into g_ENT[0].
// ---------------------------------------------------------------------------
__global__ void __launch_bounds__(256) kR_reduce() {
    int i = blockIdx.x * 512 + threadIdx.x;
    #pragma unroll
    for (int t = 0; t < 2; t++, i += 256) {
        float4 a = ((const float4*)g_ENT[0])[i];
        #pragma unroll
        for (int p = 1; p < KSPLIT; p++) {
            float4 b = ((const float4*)g_ENT[p])[i];
            a.x += b.x; a.y += b.y; a.z += b.z; a.w += b.w;
        }
        ((float4*)g_ENT[0])[i] = a;
    }
}

// ---------------------------------------------------------------------------
// K3: out[b,s,:] = word_embedding[ids[b,s]] + sum_e mask[b,e,s] * ent[b*E+e,:]
// 4 rows per block -> 4096 blocks x 192 threads. (round-4 form, 14.9us)
// ---------------------------------------------------------------------------
__global__ void __launch_bounds__(192) k3_fuse(const int*   __restrict__ ids,
                                               const float* __restrict__ mask,
                                               const float* __restrict__ we,
                                               float*       __restrict__ out) {
    const int rblk = blockIdx.x;          // 4096
    const int b    = rblk >> 7;
    const int s0   = (rblk & 127) << 2;
    const int row0 = b * S_ + s0;
    const int tid  = threadIdx.x;

    __shared__ float    sm[E_][4];
    __shared__ unsigned sflag;

    int wid0 = __ldg(ids + row0 + 0);
    int wid1 = __ldg(ids + row0 + 1);
    int wid2 = __ldg(ids + row0 + 2);
    int wid3 = __ldg(ids + row0 + 3);

    const float4* __restrict__ we4 = (const float4*)we;
    float4 v0 = we4[(long long)wid0 * (H_ / 4) + tid];
    float4 v1 = we4[(long long)wid1 * (H_ / 4) + tid];
    float4 v2 = we4[(long long)wid2 * (H_ / 4) + tid];
    float4 v3 = we4[(long long)wid3 * (H_ / 4) + tid];

    if (tid < 32) {
        int e  = tid >> 2;
        int rr = tid & 3;
        float m = __ldg(mask + (b * E_ + e) * S_ + s0 + rr);
        sm[e][rr] = m;
        unsigned bal = __ballot_sync(0xffffffffu, m != 0.0f);
        if (tid == 0) sflag = bal;
    }
    __syncthreads();

    const unsigned flag = sflag;
    if (flag) {
        const float4* __restrict__ ent4 = (const float4*)g_ENT[0];
        #pragma unroll
        for (int e = 0; e < E_; e++) {
            unsigned f4 = (flag >> (e * 4)) & 0xFu;
            if (f4) {
                float4 p = ent4[(b * E_ + e) * (H_ / 4) + tid];
                if (f4 & 1u) { float m = sm[e][0];
                    v0.x = fmaf(m, p.x, v0.x); v0.y = fmaf(m, p.y, v0.y);
                    v0.z = fmaf(m, p.z, v0.z); v0.w = fmaf(m, p.w, v0.w); }
                if (f4 & 2u) { float m = sm[e][1];
                    v1.x = fmaf(m, p.x, v1.x); v1.y = fmaf(m, p.y, v1.y);
                    v1.z = fmaf(m, p.z, v1.z); v1.w = fmaf(m, p.w, v1.w); }
                if (f4 & 4u) { float m = sm[e][2];
                    v2.x = fmaf(m, p.x, v2.x); v2.y = fmaf(m, p.y, v2.y);
                    v2.z = fmaf(m, p.z, v2.z); v2.w = fmaf(m, p.w, v2.w); }
                if (f4 & 8u) { float m = sm[e][3];
                    v3.x = fmaf(m, p.x, v3.x); v3.y = fmaf(m, p.y, v3.y);
                    v3.z = fmaf(m, p.z, v3.z); v3.w = fmaf(m, p.w, v3.w); }
            }
        }
    }

    float4* __restrict__ out4 = (float4*)out;
    out4[(long long)(row0 + 0) * (H_ / 4) + tid] = v0;
    out4[(long long)(row0 + 1) * (H_ / 4) + tid] = v1;
    out4[(long long)(row0 + 2) * (H_ / 4) + tid] = v2;
    out4[(long long)(row0 + 3) * (H_ / 4) + tid] = v3;
}

// ---------------------------------------------------------------------------
extern "C" void kernel_launch(void* const* d_in, const int* in_sizes, int n_in,
                              void* d_out, int out_size) {
    const int*   ids  = (const int*)  d_in[0];
    const float* X    = (const float*)d_in[1];
    const float* msk  = (const float*)d_in[2];
    const float* we   = (const float*)d_in[3];
    const float* W1   = (const float*)d_in[4];
    const float* b1   = (const float*)d_in[5];
    const float* W2   = (const float*)d_in[6];
    const float* b2   = (const float*)d_in[7];
    float* out = (float*)d_out;

    cudaFuncSetAttribute(k1_mlp1, cudaFuncAttributeMaxDynamicSharedMemorySize, SMEM1);
    cudaFuncSetAttribute(k2_mlp2, cudaFuncAttributeMaxDynamicSharedMemorySize, SMEM2);

    k1_mlp1<<<dim3(4, 32), 256, SMEM1>>>(X, W1, b1);
    k2_mlp2<<<dim3(6, 4, KSPLIT), 256, SMEM2>>>(W2, b2);
    kR_reduce<<<96, 256>>>();
    k3_fuse<<<4096, 192>>>(ids, msk, we, out);
}

// round 7
// speedup vs baseline: 1.8022x; 1.0006x over previous
#include <cuda_runtime.h>

#define B_   32
#define S_   512
#define E_   8
#define H_   768
#define KG_  100
#define MH_  1000
#define NROW (B_*E_)     /* 256 */
#define KSPLIT 6
#define KC   167         /* ceil(1000/6) */
#define KPAD 168

typedef unsigned long long u64;

// Scratch (device globals — no allocation allowed)
__device__ float g_Hs[NROW * MH_];                       // 256x1000 post-relu hidden
__device__ __align__(16) float g_ENT[KSPLIT][NROW * H_]; // K-split partials of ent

// ---- packed fp32x2 helpers (sm_100+ PTX) ----------------------------------
__device__ __forceinline__ u64 pk2(float a, float b) {
    u64 r; asm("mov.b64 %0, {%1,%2};" : "=l"(r) : "f"(a), "f"(b)); return r;
}
__device__ __forceinline__ u64 fma2(u64 a, u64 b, u64 c) {
    u64 d; asm("fma.rn.f32x2 %0, %1, %2, %3;" : "=l"(d) : "l"(a), "l"(b), "l"(c)); return d;
}
__device__ __forceinline__ float2 up2(u64 v) {
    float2 f; asm("mov.b64 {%0,%1}, %2;" : "=f"(f.x), "=f"(f.y) : "l"(v)); return f;
}

#define SMEM1 (KG_*256*4 + 4*KG_*8)          /* 105600 B */
#define SMEM2 (KPAD*128*4 + 64*KPAD*8)       /* 172032 B */

// ---------------------------------------------------------------------------
// K1: Hs = relu(X @ W1 + b1)
// grid (4, 32), block 512 (16 warps). Block covers 256 cols x 8 rows.
// tid&255 -> col, tid>>8 -> row half (rows 0-3 / 4-7). 2 FFMA2 per k/thread.
// ---------------------------------------------------------------------------
__global__ void __launch_bounds__(512) k1_mlp1(const float* __restrict__ X,
                                               const float* __restrict__ W1,
                                               const float* __restrict__ b1) {
    extern __shared__ char smraw1[];
    float* sw1 = (float*)smraw1;                    // [100][256]
    u64*   xp  = (u64*)(smraw1 + KG_ * 256 * 4);    // [4][100] row-pair dups

    const int cb = blockIdx.x * 256;
    const int rb = blockIdx.y * 8;
    const int tid = threadIdx.x;

    const float4* __restrict__ W14 = (const float4*)W1;   // 250 f4 per row
    const int c4base = cb >> 2;

    for (int idx = tid; idx < KG_ * 64; idx += 512) {      // 100 rows x 64 f4
        int row = idx >> 6, c = idx & 63;
        float4 v = make_float4(0.f, 0.f, 0.f, 0.f);
        if (c4base + c < MH_ / 4)
            v = W14[row * (MH_ / 4) + c4base + c];
        *(float4*)(sw1 + row * 256 + c * 4) = v;
    }
    for (int idx = tid; idx < 4 * KG_; idx += 512) {
        int p = idx / KG_, k = idx - p * KG_;
        xp[p * KG_ + k] = pk2(X[(rb + 2*p) * KG_ + k], X[(rb + 2*p + 1) * KG_ + k]);
    }
    __syncthreads();

    const int c    = tid & 255;
    const int half = tid >> 8;                 // 0: rows 0-3, 1: rows 4-7
    const int j    = cb + c;
    if (j < MH_) {
        const float bj = b1[j];
        u64 acc0 = pk2(bj, bj);
        u64 acc1 = acc0;
        const u64* xp0 = xp + (2 * half) * KG_;
        const u64* xp1 = xp + (2 * half + 1) * KG_;

        #pragma unroll 10
        for (int k = 0; k < KG_; k++) {
            float w = sw1[k * 256 + c];
            u64 wp = pk2(w, w);
            acc0 = fma2(xp0[k], wp, acc0);
            acc1 = fma2(xp1[k], wp, acc1);
        }
        float2 a0 = up2(acc0), a1 = up2(acc1);
        int r = rb + 4 * half;
        g_Hs[(r + 0) * MH_ + j] = fmaxf(a0.x, 0.0f);
        g_Hs[(r + 1) * MH_ + j] = fmaxf(a0.y, 0.0f);
        g_Hs[(r + 2) * MH_ + j] = fmaxf(a1.x, 0.0f);
        g_Hs[(r + 3) * MH_ + j] = fmaxf(a1.y, 0.0f);
    }
}

// ---------------------------------------------------------------------------
// K2: ENT_part[kz] = Hs[:, kchunk] @ W2[kchunk, :]  (+ b2 folded into kz==0)
// grid (6, 4, 6) = 144 blocks (1/SM), block 512 (16 warps, 4/SMSP).
// tx -> 4 cols, ty (0..15) -> 4 rows. W2 tile + duplicated-pair h tile in
// smem; inner loop = 1 LDS.128 + 4 broadcast LDS.64 + 8 FFMA2 per k.
// ---------------------------------------------------------------------------
__global__ void __launch_bounds__(512) k2_mlp2(const float* __restrict__ W2,
                                               const float* __restrict__ b2) {
    extern __shared__ char smraw2[];
    float* sw2 = (float*)smraw2;                    // [168][128]
    u64*   shd = (u64*)(smraw2 + KPAD * 128 * 4);   // [64][168] dup pairs

    const int cbase = blockIdx.x * 128;
    const int rb = blockIdx.y * 64;
    const int kz = blockIdx.z;
    const int kb = kz * KC;
    const int tid = threadIdx.x;
    const int tx = tid & 31;
    const int ty = tid >> 5;                        // 0..15

    // Stage W2 tile: 168 rows x 32 f4.
    const float4* __restrict__ W24 = (const float4*)W2;
    for (int idx = tid; idx < KPAD * 32; idx += 512) {
        int row = idx >> 5, cc = idx & 31;
        int kk = kb + row;
        float4 v = make_float4(0.f, 0.f, 0.f, 0.f);
        if (row < KC && kk < MH_)
            v = W24[kk * (H_ / 4) + (cbase >> 2) + cc];
        *(float4*)(sw2 + row * 128 + cc * 4) = v;
    }

    // Stage h tile as duplicated pairs: warp ty handles rows ty, ty+16, ...
    #pragma unroll
    for (int rr = 0; rr < 4; rr++) {
        int r = rr * 16 + ty;
        const float* hrow = g_Hs + (rb + r) * MH_ + kb;
        for (int k = tx; k < KPAD; k += 32) {
            float v = (k < KC && kb + k < MH_) ? hrow[k] : 0.0f;
            shd[r * KPAD + k] = pk2(v, v);
        }
    }
    __syncthreads();

    const int col = cbase + tx * 4;
    const int r0 = ty * 4;

    u64 acc[4][2];
    if (kz == 0) {
        float4 bv = *(const float4*)(b2 + col);
        u64 p0 = pk2(bv.x, bv.y), p1 = pk2(bv.z, bv.w);
        #pragma unroll
        for (int i = 0; i < 4; i++) { acc[i][0] = p0; acc[i][1] = p1; }
    } else {
        #pragma unroll
        for (int i = 0; i < 4; i++) { acc[i][0] = 0ULL; acc[i][1] = 0ULL; }
    }

    #pragma unroll 4
    for (int k = 0; k < KPAD; k++) {
        float4 w = *(const float4*)(sw2 + k * 128 + tx * 4);
        u64 wp0 = pk2(w.x, w.y), wp1 = pk2(w.z, w.w);
        #pragma unroll
        for (int i = 0; i < 4; i++) {
            u64 h = shd[(r0 + i) * KPAD + k];       // broadcast LDS.64
            acc[i][0] = fma2(h, wp0, acc[i][0]);
            acc[i][1] = fma2(h, wp1, acc[i][1]);
        }
    }

    float* dst = g_ENT[kz];
    #pragma unroll
    for (int i = 0; i < 4; i++) {
        int r = rb + r0 + i;
        float2 a0 = up2(acc[i][0]), a1 = up2(acc[i][1]);
        *(float4*)(dst + r * H_ + col) = make_float4(a0.x, a0.y, a1.x, a1.y);
    }
}

// ---------------------------------------------------------------------------
// K3: out = gather + masked entity add; sums the 6 ENT partials inline on the
// (rare) nonzero path. 4 rows per block -> 4096 blocks x 192 threads.
// ---------------------------------------------------------------------------
__global__ void __launch_bounds__(192) k3_fuse(const int*   __restrict__ ids,
                                               const float* __restrict__ mask,
                                               const float* __restrict__ we,
                                               float*       __restrict__ out) {
    const int rblk = blockIdx.x;          // 4096
    const int b    = rblk >> 7;
    const int s0   = (rblk & 127) << 2;
    const int row0 = b * S_ + s0;
    const int tid  = threadIdx.x;

    __shared__ float    sm[E_][4];
    __shared__ unsigned sflag;

    int wid0 = __ldg(ids + row0 + 0);
    int wid1 = __ldg(ids + row0 + 1);
    int wid2 = __ldg(ids + row0 + 2);
    int wid3 = __ldg(ids + row0 + 3);

    const float4* __restrict__ we4 = (const float4*)we;
    float4 v0 = we4[(long long)wid0 * (H_ / 4) + tid];
    float4 v1 = we4[(long long)wid1 * (H_ / 4) + tid];
    float4 v2 = we4[(long long)wid2 * (H_ / 4) + tid];
    float4 v3 = we4[(long long)wid3 * (H_ / 4) + tid];

    if (tid < 32) {
        int e  = tid >> 2;
        int rr = tid & 3;
        float m = __ldg(mask + (b * E_ + e) * S_ + s0 + rr);
        sm[e][rr] = m;
        unsigned bal = __ballot_sync(0xffffffffu, m != 0.0f);
        if (tid == 0) sflag = bal;
    }
    __syncthreads();

    const unsigned flag = sflag;
    if (flag) {
        #pragma unroll
        for (int e = 0; e < E_; e++) {
            unsigned f4 = (flag >> (e * 4)) & 0xFu;
            if (f4) {
                const int idx = (b * E_ + e) * (H_ / 4) + tid;
                float4 p = ((const float4*)g_ENT[0])[idx];
                #pragma unroll
                for (int q = 1; q < KSPLIT; q++) {
                    float4 t = ((const float4*)g_ENT[q])[idx];
                    p.x += t.x; p.y += t.y; p.z += t.z; p.w += t.w;
                }
                if (f4 & 1u) { float m = sm[e][0];
                    v0.x = fmaf(m, p.x, v0.x); v0.y = fmaf(m, p.y, v0.y);
                    v0.z = fmaf(m, p.z, v0.z); v0.w = fmaf(m, p.w, v0.w); }
                if (f4 & 2u) { float m = sm[e][1];
                    v1.x = fmaf(m, p.x, v1.x); v1.y = fmaf(m, p.y, v1.y);
                    v1.z = fmaf(m, p.z, v1.z); v1.w = fmaf(m, p.w, v1.w); }
                if (f4 & 4u) { float m = sm[e][2];
                    v2.x = fmaf(m, p.x, v2.x); v2.y = fmaf(m, p.y, v2.y);
                    v2.z = fmaf(m, p.z, v2.z); v2.w = fmaf(m, p.w, v2.w); }
                if (f4 & 8u) { float m = sm[e][3];
                    v3.x = fmaf(m, p.x, v3.x); v3.y = fmaf(m, p.y, v3.y);
                    v3.z = fmaf(m, p.z, v3.z); v3.w = fmaf(m, p.w, v3.w); }
            }
        }
    }

    float4* __restrict__ out4 = (float4*)out;
    out4[(long long)(row0 + 0) * (H_ / 4) + tid] = v0;
    out4[(long long)(row0 + 1) * (H_ / 4) + tid] = v1;
    out4[(long long)(row0 + 2) * (H_ / 4) + tid] = v2;
    out4[(long long)(row0 + 3) * (H_ / 4) + tid] = v3;
}

// ---------------------------------------------------------------------------
extern "C" void kernel_launch(void* const* d_in, const int* in_sizes, int n_in,
                              void* d_out, int out_size) {
    const int*   ids  = (const int*)  d_in[0];
    const float* X    = (const float*)d_in[1];
    const float* msk  = (const float*)d_in[2];
    const float* we   = (const float*)d_in[3];
    const float* W1   = (const float*)d_in[4];
    const float* b1   = (const float*)d_in[5];
    const float* W2   = (const float*)d_in[6];
    const float* b2   = (const float*)d_in[7];
    float* out = (float*)d_out;

    cudaFuncSetAttribute(k1_mlp1, cudaFuncAttributeMaxDynamicSharedMemorySize, SMEM1);
    cudaFuncSetAttribute(k2_mlp2, cudaFuncAttributeMaxDynamicSharedMemorySize, SMEM2);

    k1_mlp1<<<dim3(4, 32), 512, SMEM1>>>(X, W1, b1);
    k2_mlp2<<<dim3(6, 4, KSPLIT), 512, SMEM2>>>(W2, b2);
    k3_fuse<<<4096, 192>>>(ids, msk, we, out);
}